// round 7
// baseline (speedup 1.0000x reference)
#include <cuda_runtime.h>
#include <cstdint>

// Foveated tokenizer: 5-level box-average pyramid over (3,4096,4096) int32 image.
// Token boxes exactly partition the image -> each pixel read exactly once.
// Pure DRAM-streaming kernel; ~201 MB read + 3 MB write (float32 out).
// R4: int4 (LDG.128) vectorized phase 1 -> 4x fewer load instructions,
//     4x more bytes in flight per thread.

#define IMG_DIM 4096
#define IMG_CH_STRIDE (IMG_DIM * IMG_DIM)

// Job layout (heavy levels first for wave-1 scheduling):
//   level 4 (s=16): 192 tok * 3 ch * 16 chunks = 9216 jobs   [0, 9216)
//   level 3 (s= 8): 192 tok * 3 ch *  4 chunks = 2304 jobs   [9216, 11520)
//   level 2 (s= 4): 192 tok * 3 ch *  1 chunk  =  576 jobs   [11520, 12096)
//   level 1 (s= 2): 192 tok * 3 ch *  1 chunk  =  576 jobs   [12096, 12672)
//   level 0 (s= 1): 256 tok * 3 ch *  1 chunk  =  768 jobs   [12672, 13440)
#define N_JOBS 13440

template <int LEVEL>
__device__ __forceinline__ void process_level(int job,
                                              const int* __restrict__ img,
                                              float* __restrict__ out,
                                              int* colsum) {
    constexpr int S   = 1 << LEVEL;            // box stride in pixels
    constexpr int CHK = (LEVEL == 4) ? 16 : (LEVEL == 3) ? 4 : 1;  // chunks/(tok,ch)
    constexpr int NR  = 16 / CHK;              // output rows per chunk
    constexpr int W   = 16 * S;                // region width in pixels
    constexpr int SHW = 4 + LEVEL;             // log2(W)
    constexpr int TOTAL = NR * W;              // colsum entries (<= 1024)
    constexpr int TOTV  = TOTAL / 4;           // int4 entries
    constexpr int SHWV  = SHW - 2;             // log2(W/4)
    constexpr int TOKBASE =
        (LEVEL == 0) ? 0 : (LEVEL == 1) ? 256 : (LEVEL == 2) ? 448
                                            : (LEVEL == 3) ? 640 : 832;
    constexpr int PER_TOK = 3 * CHK;
    constexpr int CORNER  = 2048 - 128 * S;    // pixel offset of level's grid (16-aligned)
    constexpr int UNROLL  = (S < 8) ? S : 8;   // cap in-flight LDG.128 per thread at 8

    const int tl    = job / PER_TOK;           // token index within level
    const int rem   = job - tl * PER_TOK;
    const int ch    = rem / CHK;
    const int chunk = rem - ch * CHK;

    // Map level-local token index -> (row, col) on the 16x16 coarse grid.
    int row, col;
    if (LEVEL == 0) {
        row = tl >> 4; col = tl & 15;
    } else {
        // ring = 4 at every level >= 1:
        //   j <  64 : top 4 rows, full width
        //   j < 128 : middle 8 rows, 4 left + 4 right columns each
        //   else    : bottom 4 rows, full width
        if (tl < 64)       { row = tl >> 4;             col = tl & 15; }
        else if (tl < 128) { int k = tl - 64; row = 4 + (k >> 3);
                             int r = k & 7;             col = (r < 4) ? r : (r + 8); }
        else               { int k = tl - 128; row = 12 + (k >> 4); col = k & 15; }
    }

    const int cx  = CORNER + W * col;          // region top-left pixel (16-aligned)
    const int cy  = CORNER + W * row;
    const int oy0 = chunk * NR;                // first output row of this chunk

    const int* base = img + (size_t)ch * IMG_CH_STRIDE;
    const int tid = threadIdx.x;

    // Phase 1: column sums, int4-vectorized. Each thread owns 4 adjacent
    // columns; per warp per row-load: 512B contiguous (4 sectors).
    for (int v = tid; v < TOTV; v += 256) {
        const int oy = v >> SHWV;                  // local output row
        const int xv = (v & ((W / 4) - 1)) << 2;   // first column of this vec
        const int4* p = (const int4*)(base +
            (size_t)(cy + S * (oy0 + oy)) * IMG_DIM + cx + xv);
        int4 a = make_int4(0, 0, 0, 0);
#pragma unroll 1
        for (int r0 = 0; r0 < S; r0 += UNROLL) {
#pragma unroll
            for (int r = 0; r < UNROLL; r++) {
                int4 t = __ldcs(p + (size_t)r * (IMG_DIM / 4));
                a.x += t.x; a.y += t.y; a.z += t.z; a.w += t.w;
            }
            p += (size_t)UNROLL * (IMG_DIM / 4);
        }
        ((int4*)colsum)[v] = a;                    // conflict-free 16B STS
    }
    __syncthreads();

    // Phase 2: reduce S consecutive column sums per box, floor-divide, store f32.
    constexpr int NOUT = NR * 16;
    const int n = TOKBASE + tl;
    for (int o = tid; o < NOUT; o += 256) {
        const int oy = o >> 4;
        const int bx = o & 15;
        const int bi = (oy << SHW) + (bx << LEVEL);
        int sum = 0;
#pragma unroll
        for (int i = 0; i < S; i++) sum += colsum[bi + i];
        // Exact floor-div by S*S (sum >= 0); value fits in [0,255].
        out[(((size_t)n * 3 + ch) << 8) + ((size_t)(oy0 + oy) << 4) + bx] =
            (float)(sum >> (2 * LEVEL));
    }
}

__global__ void __launch_bounds__(256) foveator_kernel(const int* __restrict__ img,
                                                       float* __restrict__ out) {
    __shared__ int colsum[1024];
    const int b = blockIdx.x;
    if (b < 9216)       process_level<4>(b,          img, out, colsum);
    else if (b < 11520) process_level<3>(b - 9216,   img, out, colsum);
    else if (b < 12096) process_level<2>(b - 11520,  img, out, colsum);
    else if (b < 12672) process_level<1>(b - 12096,  img, out, colsum);
    else                process_level<0>(b - 12672,  img, out, colsum);
}

extern "C" void kernel_launch(void* const* d_in, const int* in_sizes, int n_in,
                              void* d_out, int out_size) {
    const int* img = (const int*)d_in[0];
    float* out = (float*)d_out;
    foveator_kernel<<<N_JOBS, 256>>>(img, out);
}

// round 8
// speedup vs baseline: 1.3569x; 1.3569x over previous
#include <cuda_runtime.h>
#include <cstdint>

// Foveated tokenizer: 5-level box-average pyramid over (3,4096,4096) int32 image.
// Token boxes exactly partition the image -> each pixel read exactly once.
// ~201 MB read + 3 MB write (float32 out), pure DRAM stream.
// R7: 2-D (vec-col x row-group) decomposition -> ALL 256 threads issue LDG.128;
//     fatter level-3/4 chunks (RPT=8, 32KB/CTA), grid 13440 -> 7680.

#define IMG_DIM 4096
#define IMG_CH_STRIDE (IMG_DIM * IMG_DIM)

// Job layout (heavy levels first for wave-1 scheduling):
//   level 4 (s=16): 192 tok * 3 ch * 8 chunks = 4608 jobs   [0, 4608)
//   level 3 (s= 8): 192 tok * 3 ch * 2 chunks = 1152 jobs   [4608, 5760)
//   level 2 (s= 4): 192 tok * 3 ch * 1 chunk  =  576 jobs   [5760, 6336)
//   level 1 (s= 2): 192 tok * 3 ch * 1 chunk  =  576 jobs   [6336, 6912)
//   level 0 (s= 1): 256 tok * 3 ch * 1 chunk  =  768 jobs   [6912, 7680)
#define N_JOBS 7680

template <int LEVEL>
__device__ __forceinline__ void process_level(int job,
                                              const int* __restrict__ img,
                                              float* __restrict__ out,
                                              int* psum) {
    constexpr int S    = 1 << LEVEL;           // box stride in pixels
    constexpr int CHK  = (LEVEL == 4) ? 8 : (LEVEL == 3) ? 2 : 1; // chunks/(tok,ch)
    constexpr int NR   = 16 / CHK;             // output rows per chunk
    constexpr int W    = 16 * S;               // region width in pixels
    constexpr int VC   = W / 4;                // int4 columns
    constexpr int ROWS = NR * S;               // image rows per chunk
    constexpr int ITEMS = ROWS * VC;           // (row, vcol) load items
    constexpr int RPT  = (ITEMS >= 1024) ? ITEMS / 256 : 1;  // rows per thread
    constexpr int NACT = ITEMS / RPT;          // active threads in phase 1
    constexpr int NG   = S / RPT > 0 ? ((S / RPT) ? S / RPT : 1) : 1; // groups per out-row
    constexpr int NGE  = (S >= RPT) ? S / RPT : 1;
    constexpr int TOKBASE =
        (LEVEL == 0) ? 0 : (LEVEL == 1) ? 256 : (LEVEL == 2) ? 448
                                            : (LEVEL == 3) ? 640 : 832;
    constexpr int PER_TOK = 3 * CHK;
    constexpr int CORNER  = 2048 - 128 * S;    // pixel offset of level's grid (16-aligned)

    const int tl    = job / PER_TOK;           // token index within level
    const int rem   = job - tl * PER_TOK;
    const int ch    = rem / CHK;
    const int chunk = rem - ch * CHK;

    // Map level-local token index -> (row, col) on the 16x16 coarse grid.
    int row, col;
    if (LEVEL == 0) {
        row = tl >> 4; col = tl & 15;
    } else {
        // ring = 4 at every level >= 1
        if (tl < 64)       { row = tl >> 4;             col = tl & 15; }
        else if (tl < 128) { int k = tl - 64; row = 4 + (k >> 3);
                             int r = k & 7;             col = (r < 4) ? r : (r + 8); }
        else               { int k = tl - 128; row = 12 + (k >> 4); col = k & 15; }
    }

    const int cx  = CORNER + W * col;          // region top-left pixel (16B aligned)
    const int cy  = CORNER + W * row;
    const int oy0 = chunk * NR;                // first output row of this chunk
    const int ry0 = cy + S * oy0;              // first image row of this chunk

    const int* base = img + (size_t)ch * IMG_CH_STRIDE;
    const int tid = threadIdx.x;

    // Phase 1: every active thread owns one int4 column slice of RPT rows.
    // Fully unrolled -> RPT front-batched LDG.128 (128B in flight/thread at RPT=8).
    if (tid < NACT) {
        const int vcol = tid & (VC - 1);
        const int g    = tid / VC;             // row-group index
        const int4* p  = (const int4*)(base + (size_t)(ry0 + g * RPT) * IMG_DIM + cx)
                         + vcol;
        int4 a = make_int4(0, 0, 0, 0);
#pragma unroll
        for (int r = 0; r < RPT; r++) {
            int4 t = __ldcs(p);
            p += IMG_DIM / 4;
            a.x += t.x; a.y += t.y; a.z += t.z; a.w += t.w;
        }
        ((int4*)psum)[g * VC + vcol] = a;      // conflict-free 16B STS
    }
    __syncthreads();

    // Phase 2: combine NGE row-group partials x S scalar columns per output box.
    constexpr int NOUT = NR * 16;
    const int n = TOKBASE + tl;
    for (int o = tid; o < NOUT; o += 256) {
        const int oy = o >> 4;
        const int bx = o & 15;
        int sum = 0;
#pragma unroll
        for (int gg = 0; gg < NGE; gg++) {
            const int* s = psum + (oy * NGE + gg) * W + (bx << LEVEL);
#pragma unroll
            for (int i = 0; i < S; i++) sum += s[i];
        }
        // Exact floor-div by S*S (sum >= 0); value fits in [0,255].
        out[(((size_t)n * 3 + ch) << 8) + ((size_t)(oy0 + oy) << 4) + bx] =
            (float)(sum >> (2 * LEVEL));
    }
    (void)NG;
}

__global__ void __launch_bounds__(256) foveator_kernel(const int* __restrict__ img,
                                                       float* __restrict__ out) {
    __shared__ int psum[1024];                 // 256 int4 partials max (4KB)
    const int b = blockIdx.x;
    if (b < 4608)      process_level<4>(b,         img, out, psum);
    else if (b < 5760) process_level<3>(b - 4608,  img, out, psum);
    else if (b < 6336) process_level<2>(b - 5760,  img, out, psum);
    else if (b < 6912) process_level<1>(b - 6336,  img, out, psum);
    else               process_level<0>(b - 6912,  img, out, psum);
}

extern "C" void kernel_launch(void* const* d_in, const int* in_sizes, int n_in,
                              void* d_out, int out_size) {
    const int* img = (const int*)d_in[0];
    float* out = (float*)d_out;
    foveator_kernel<<<N_JOBS, 256>>>(img, out);
}